// round 1
// baseline (speedup 1.0000x reference)
#include <cuda_runtime.h>

#define EMB 256
#define HID 64
#define MAXN 100000
#define MAXE 1200000
#define MAXQ 8192

// ---------------- scratch (device globals; no allocation) ----------------
__device__ int   g_slot[MAXN];        // node -> compact slot (query index) or -1
__device__ float g_s[MAXQ * EMB];     // per-slot aggregated sum_e w_e * emb[src_e]
__device__ float g_c[MAXQ];           // per-slot sum_e w_e
__device__ int   g_fsrc[MAXE];        // filtered edges: src node
__device__ int   g_fslot[MAXE];       // filtered edges: dst slot
__device__ float g_fw[MAXE];          // filtered edges: weight
__device__ int   g_count;             // filtered edge count

// ---------------- kernels ----------------
__global__ void k_init(int n_nodes) {
    int i = blockIdx.x * blockDim.x + threadIdx.x;
    if (i < n_nodes)     g_slot[i] = -1;
    if (i < MAXQ * EMB)  g_s[i] = 0.0f;
    if (i < MAXQ)        g_c[i] = 0.0f;
    if (i == 0)          g_count = 0;
}

__global__ void k_mark(const int* __restrict__ query, int Q) {
    int i = blockIdx.x * blockDim.x + threadIdx.x;
    if (i < Q) {
        atomicCAS(&g_slot[query[i]], -1, i);  // first query index wins; unique slot per node
    }
}

__global__ void k_filter(const int* __restrict__ src, const int* __restrict__ dst,
                         const float* __restrict__ ew, int E) {
    int e = blockIdx.x * blockDim.x + threadIdx.x;
    if (e >= E) return;
    int sl = g_slot[dst[e]];
    if (sl >= 0) {
        int p = atomicAdd(&g_count, 1);       // ptxas warp-aggregates this
        g_fsrc[p]  = src[e];
        g_fslot[p] = sl;
        g_fw[p]    = ew[e];
    }
}

// One warp per filtered edge: s[slot] += w * emb[src] (256 floats = 64 float4)
__global__ void __launch_bounds__(256) k_scatter(const float* __restrict__ emb) {
    int gw   = (blockIdx.x * blockDim.x + threadIdx.x) >> 5;
    int nw   = (gridDim.x * blockDim.x) >> 5;
    int lane = threadIdx.x & 31;
    int cnt  = g_count;
    for (int i = gw; i < cnt; i += nw) {
        int   sn = g_fsrc[i];
        int   sl = g_fslot[i];
        float w  = g_fw[i];
        const float4* er = (const float4*)(emb + (size_t)sn * EMB);
        float4* srow = (float4*)(g_s + (size_t)sl * EMB);
#pragma unroll
        for (int j = 0; j < 2; ++j) {
            float4 v = er[lane + 32 * j];
            float4 d = make_float4(v.x * w, v.y * w, v.z * w, v.w * w);
            atomicAdd(&srow[lane + 32 * j], d);   // sm_90+ vector red.global.add.v4.f32
        }
        if (lane == 0) atomicAdd(&g_c[sl], w);
    }
}

// Fused readout: out[q] = Wr . relu(Ws@emb[q] + bs + Wn@s[slot_q] + c_q*bn) + br
// Treated as [Q x 512] @ [512 x 64] with weights staged transposed in smem.
#define WPAD 65               // 512 x 65 floats (conflict-free: 65 % 32 == 1)
#define GPAD 520              // 32 x 520 floats (520*4 = 2080 B, 16B aligned rows)
#define SMEM_BYTES ((512 * WPAD + 32 * GPAD + 32) * 4)

__global__ void __launch_bounds__(256) k_readout(
    const float* __restrict__ emb, const float* __restrict__ Ws,
    const float* __restrict__ bs,  const float* __restrict__ Wn,
    const float* __restrict__ bn,  const float* __restrict__ Wr,
    const float* __restrict__ br,  const int* __restrict__ query,
    float* __restrict__ out, int Q)
{
    extern __shared__ float sm[];
    float* Wsm = sm;                    // [512][WPAD]  (k-major, oi contiguous)
    float* gsm = sm + 512 * WPAD;       // [32][GPAD]   (concat emb|s per query)
    float* csm = gsm + 32 * GPAD;       // [32]

    int tid   = threadIdx.x;
    int qbase = blockIdx.x * 32;

    // Stage weights transposed: Wsm[k][oi] = Ws[oi][k]; Wsm[256+k][oi] = Wn[oi][k]
    for (int i = tid; i < HID * EMB; i += 256) {
        int oi = i >> 8, k = i & 255;   // coalesced global read, padded STS
        Wsm[k * WPAD + oi]         = Ws[i];
        Wsm[(k + 256) * WPAD + oi] = Wn[i];
    }
    // Stage per-query inputs: gsm[q][0:256) = emb[node], gsm[q][256:512) = s[slot]
    for (int i = tid; i < 32 * 128; i += 256) {
        int q = i >> 7, part = i & 127;
        if (qbase + q < Q) {
            int node = query[qbase + q];
            int sl   = g_slot[node];
            float4 v;
            if (part < 64) v = ((const float4*)(emb + (size_t)node * EMB))[part];
            else           v = ((const float4*)(g_s + (size_t)sl * EMB))[part - 64];
            ((float4*)(gsm + q * GPAD))[part] = v;
            if (part == 0) csm[q] = g_c[sl];
        } else {
            ((float4*)(gsm + q * GPAD))[part] = make_float4(0.f, 0.f, 0.f, 0.f);
            if (part == 0) csm[q] = 0.f;
        }
    }
    __syncthreads();

    int lane = tid & 31;     // owns h-rows lane, lane+32
    int grp  = tid >> 5;     // warp handles queries grp, grp+8, grp+16, grp+24
    float bs0 = bs[lane], bs1 = bs[lane + 32];
    float bn0 = bn[lane], bn1 = bn[lane + 32];

    float a0[4], a1[4];
#pragma unroll
    for (int j = 0; j < 4; ++j) {
        float cc = csm[grp + 8 * j];
        a0[j] = bs0 + cc * bn0;
        a1[j] = bs1 + cc * bn1;
    }

    const float* g0 = gsm + grp * GPAD;
#pragma unroll 4
    for (int k = 0; k < 512; ++k) {
        float w0 = Wsm[k * WPAD + lane];
        float w1 = Wsm[k * WPAD + lane + 32];
#pragma unroll
        for (int j = 0; j < 4; ++j) {
            float gv = g0[(8 * j) * GPAD + k];   // broadcast across warp
            a0[j] += w0 * gv;
            a1[j] += w1 * gv;
        }
    }

    float wr0 = Wr[lane], wr1 = Wr[lane + 32];
    float brv = br[0];
#pragma unroll
    for (int j = 0; j < 4; ++j) {
        float r = wr0 * fmaxf(a0[j], 0.f) + wr1 * fmaxf(a1[j], 0.f);
#pragma unroll
        for (int o = 16; o > 0; o >>= 1) r += __shfl_xor_sync(0xffffffffu, r, o);
        int q = qbase + grp + 8 * j;
        if (lane == 0 && q < Q) out[q] = r + brv;
    }
}

// ---------------- launch ----------------
extern "C" void kernel_launch(void* const* d_in, const int* in_sizes, int n_in,
                              void* d_out, int out_size) {
    const float* emb = (const float*)d_in[0];
    const float* ew  = (const float*)d_in[1];
    const float* Ws  = (const float*)d_in[2];
    const float* bs  = (const float*)d_in[3];
    const float* Wn  = (const float*)d_in[4];
    const float* bn  = (const float*)d_in[5];
    const float* Wr  = (const float*)d_in[6];
    const float* br  = (const float*)d_in[7];
    const int*   src = (const int*)d_in[8];
    const int*   dst = (const int*)d_in[9];
    const int*   qry = (const int*)d_in[10];

    int N = in_sizes[0] / EMB;
    int E = in_sizes[8];
    int Q = in_sizes[10];

    cudaFuncSetAttribute(k_readout, cudaFuncAttributeMaxDynamicSharedMemorySize, SMEM_BYTES);

    int initN = MAXQ * EMB;  // covers all init targets
    k_init   <<<(initN + 255) / 256, 256>>>(N);
    k_mark   <<<(Q + 255) / 256, 256>>>(qry, Q);
    k_filter <<<(E + 255) / 256, 256>>>(src, dst, ew, E);
    k_scatter<<<1184, 256>>>(emb);
    k_readout<<<(Q + 31) / 32, 256, SMEM_BYTES>>>(emb, Ws, bs, Wn, bn, Wr, br, qry,
                                                  (float*)d_out, Q);
}

// round 2
// speedup vs baseline: 1.1481x; 1.1481x over previous
#include <cuda_runtime.h>

#define EMB 256
#define HID 64
#define MAXN 100000
#define MAXE 1200000
#define MAXQ 8192

// ---------------- scratch (device globals; no allocation) ----------------
__device__ int   g_slot[MAXN];        // node -> compact slot (query index) or -1
__device__ float g_s[MAXQ * EMB];     // per-slot aggregated sum_e w_e * emb[src_e]
__device__ float g_c[MAXQ];           // per-slot sum_e w_e
__device__ int   g_fsrc[MAXE];        // filtered edges: src node
__device__ int   g_fslot[MAXE];       // filtered edges: dst slot
__device__ float g_fw[MAXE];          // filtered edges: weight
__device__ int   g_count;             // filtered edge count

// ---------------- kernels ----------------
__global__ void k_init(int n_nodes) {
    int i = blockIdx.x * blockDim.x + threadIdx.x;
    if (i < MAXQ * EMB / 4) ((float4*)g_s)[i] = make_float4(0.f, 0.f, 0.f, 0.f);
    if (i < n_nodes)        g_slot[i] = -1;
    if (i < MAXQ)           g_c[i] = 0.0f;
    if (i == 0)             g_count = 0;
}

__global__ void k_mark(const int* __restrict__ query, int Q) {
    int i = blockIdx.x * blockDim.x + threadIdx.x;
    if (i < Q) {
        atomicCAS(&g_slot[query[i]], -1, i);  // first query index wins; unique slot per node
    }
}

__global__ void k_filter(const int* __restrict__ src, const int* __restrict__ dst,
                         const float* __restrict__ ew, int E) {
    int e = blockIdx.x * blockDim.x + threadIdx.x;
    if (e >= E) return;
    int sl = g_slot[dst[e]];
    if (sl >= 0) {
        int p = atomicAdd(&g_count, 1);       // ptxas warp-aggregates this
        g_fsrc[p]  = src[e];
        g_fslot[p] = sl;
        g_fw[p]    = ew[e];
    }
}

__device__ __forceinline__ float4 scale4(float4 v, float w) {
    return make_float4(v.x * w, v.y * w, v.z * w, v.w * w);
}

// One warp per pair of filtered edges (MLP=4): s[slot] += w * emb[src]
__global__ void __launch_bounds__(256) k_scatter(const float* __restrict__ emb) {
    int gw   = (blockIdx.x * blockDim.x + threadIdx.x) >> 5;
    int nw   = (gridDim.x * blockDim.x) >> 5;
    int lane = threadIdx.x & 31;
    int cnt  = g_count;
    int pairs = (cnt + 1) >> 1;
    for (int p = gw; p < pairs; p += nw) {
        int e0 = 2 * p, e1 = 2 * p + 1;
        bool h1 = (e1 < cnt);
        int   sn0 = g_fsrc[e0],            sl0 = g_fslot[e0];
        float w0  = g_fw[e0];
        int   sn1 = h1 ? g_fsrc[e1]  : sn0;
        int   sl1 = h1 ? g_fslot[e1] : sl0;
        float w1  = h1 ? g_fw[e1]    : 0.f;

        const float4* r0 = (const float4*)(emb + (size_t)sn0 * EMB);
        const float4* r1 = (const float4*)(emb + (size_t)sn1 * EMB);
        float4 a0 = r0[lane], b0 = r0[lane + 32];
        float4 a1 = r1[lane], b1 = r1[lane + 32];

        float4* s0 = (float4*)(g_s + (size_t)sl0 * EMB);
        atomicAdd(&s0[lane],      scale4(a0, w0));
        atomicAdd(&s0[lane + 32], scale4(b0, w0));
        if (h1) {
            float4* s1 = (float4*)(g_s + (size_t)sl1 * EMB);
            atomicAdd(&s1[lane],      scale4(a1, w1));
            atomicAdd(&s1[lane + 32], scale4(b1, w1));
        }
        if (lane == 0) {
            atomicAdd(&g_c[sl0], w0);
            if (h1) atomicAdd(&g_c[sl1], w1);
        }
    }
}

// ---------------- fused readout ----------------
// out[q] = Wr . relu(Ws@emb[node_q] + Wn@s[slot_q] + bs + c_q*bn) + br
// Register-tiled [64q x 512k] x [512k x 64o] GEMM, K in 2 chunks of 256.
#define QB   64                 // queries per block
#define KC   256                // k per chunk
#define WROW 68                 // padded row (floats), 16B aligned (68*4=272)
// dyn smem: Wsm[KC][WROW] + gsm[KC][WROW] + csm[QB] + nodes[QB] + slots[QB]
#define RD_SMEM ((KC * WROW * 2 + QB) * 4 + QB * 4 * 2)

__global__ void __launch_bounds__(256) k_readout(
    const float* __restrict__ emb, const float* __restrict__ Ws,
    const float* __restrict__ bs,  const float* __restrict__ Wn,
    const float* __restrict__ bn,  const float* __restrict__ Wr,
    const float* __restrict__ br,  const int* __restrict__ query,
    float* __restrict__ out, int Q)
{
    extern __shared__ float sm[];
    float* Wsm   = sm;                         // [KC][WROW]  (k-major, o contiguous)
    float* gsm   = sm + KC * WROW;             // [KC][WROW]  (k-major, q contiguous)
    float* csm   = gsm + KC * WROW;            // [QB]
    int*   nodes = (int*)(csm + QB);           // [QB]
    int*   slots = nodes + QB;                 // [QB]

    int tid   = threadIdx.x;
    int qbase = blockIdx.x * QB;

    if (tid < QB) {
        int q = qbase + tid;
        int node = (q < Q) ? query[q] : query[0];
        nodes[tid] = node;
        int sl = g_slot[node];
        slots[tid] = sl;
        csm[tid] = g_c[sl];
    }
    __syncthreads();

    int lane  = tid & 31;
    int w     = tid >> 5;
    int o_idx = lane & 15;          // thread outputs: o = 4*o_idx .. +3
    int q_idx = lane >> 4;          // 0/1
    int qw    = w * 8 + q_idx * 4;  // thread queries: qw .. qw+3 (block-local)

    float acc[4][4];                // [qi][oj]
#pragma unroll
    for (int a = 0; a < 4; ++a)
#pragma unroll
        for (int b = 0; b < 4; ++b) acc[a][b] = 0.f;

#pragma unroll
    for (int t = 0; t < 2; ++t) {
        // Stage weights transposed: Wsm[k][o] = W[o][k]
        const float* W = t ? Wn : Ws;
        for (int idx = tid; idx < HID * KC; idx += 256) {
            int k = idx & (KC - 1), o = idx >> 8;   // coalesced LDG, 4-way-conflict STS (cheap)
            Wsm[k * WROW + o] = W[o * EMB + k];
        }
        // Stage activations transposed: gsm[k][q] = row_q[k]
        for (int idx = tid; idx < QB * (KC / 4); idx += 256) {
            int q  = idx & (QB - 1);
            int kb = idx >> 6;
            const float* row = t ? (g_s + (size_t)slots[q] * EMB)
                                 : (emb + (size_t)nodes[q] * EMB);
            float4 v = ((const float4*)row)[kb];
            int k = kb * 4;
            gsm[(k + 0) * WROW + q] = v.x;
            gsm[(k + 1) * WROW + q] = v.y;
            gsm[(k + 2) * WROW + q] = v.z;
            gsm[(k + 3) * WROW + q] = v.w;
        }
        __syncthreads();

#pragma unroll 4
        for (int k = 0; k < KC; ++k) {
            float4 wv = *(const float4*)&Wsm[k * WROW + 4 * o_idx];
            float4 gv = *(const float4*)&gsm[k * WROW + qw];
            acc[0][0] += gv.x * wv.x; acc[0][1] += gv.x * wv.y;
            acc[0][2] += gv.x * wv.z; acc[0][3] += gv.x * wv.w;
            acc[1][0] += gv.y * wv.x; acc[1][1] += gv.y * wv.y;
            acc[1][2] += gv.y * wv.z; acc[1][3] += gv.y * wv.w;
            acc[2][0] += gv.z * wv.x; acc[2][1] += gv.z * wv.y;
            acc[2][2] += gv.z * wv.z; acc[2][3] += gv.z * wv.w;
            acc[3][0] += gv.w * wv.x; acc[3][1] += gv.w * wv.y;
            acc[3][2] += gv.w * wv.z; acc[3][3] += gv.w * wv.w;
        }
        __syncthreads();
    }

    // Epilogue: h = relu(acc + bs + c*bn); r_q = sum_o Wr[o]*h ; reduce over o lanes
    int o0 = 4 * o_idx;
    float4 bsv = *(const float4*)&bs[o0];
    float4 bnv = *(const float4*)&bn[o0];
    float4 wrv = *(const float4*)&Wr[o0];
    float  brv = br[0];
#pragma unroll
    for (int qi = 0; qi < 4; ++qi) {
        float cc = csm[qw + qi];
        float r = wrv.x * fmaxf(acc[qi][0] + bsv.x + cc * bnv.x, 0.f)
                + wrv.y * fmaxf(acc[qi][1] + bsv.y + cc * bnv.y, 0.f)
                + wrv.z * fmaxf(acc[qi][2] + bsv.z + cc * bnv.z, 0.f)
                + wrv.w * fmaxf(acc[qi][3] + bsv.w + cc * bnv.w, 0.f);
#pragma unroll
        for (int off = 8; off > 0; off >>= 1) r += __shfl_xor_sync(0xffffffffu, r, off);
        int q = qbase + qw + qi;
        if (o_idx == 0 && q < Q) out[q] = r + brv;
    }
}

// ---------------- launch ----------------
extern "C" void kernel_launch(void* const* d_in, const int* in_sizes, int n_in,
                              void* d_out, int out_size) {
    const float* emb = (const float*)d_in[0];
    const float* ew  = (const float*)d_in[1];
    const float* Ws  = (const float*)d_in[2];
    const float* bs  = (const float*)d_in[3];
    const float* Wn  = (const float*)d_in[4];
    const float* bn  = (const float*)d_in[5];
    const float* Wr  = (const float*)d_in[6];
    const float* br  = (const float*)d_in[7];
    const int*   src = (const int*)d_in[8];
    const int*   dst = (const int*)d_in[9];
    const int*   qry = (const int*)d_in[10];

    int N = in_sizes[0] / EMB;
    int E = in_sizes[8];
    int Q = in_sizes[10];

    cudaFuncSetAttribute(k_readout, cudaFuncAttributeMaxDynamicSharedMemorySize, RD_SMEM);

    int initN = MAXQ * EMB / 4;  // covers all init targets (g_s float4 fill dominates)
    k_init   <<<(initN + 255) / 256, 256>>>(N);
    k_mark   <<<(Q + 255) / 256, 256>>>(qry, Q);
    k_filter <<<(E + 255) / 256, 256>>>(src, dst, ew, E);
    k_scatter<<<1184, 256>>>(emb);
    k_readout<<<(Q + QB - 1) / QB, 256, RD_SMEM>>>(emb, Ws, bs, Wn, bn, Wr, br, qry,
                                                   (float*)d_out, Q);
}

// round 3
// speedup vs baseline: 1.5322x; 1.3345x over previous
#include <cuda_runtime.h>

#define EMB 256
#define HID 64
#define MAXN 100000
#define MAXE 1200000
#define MAXQ 8192

// ---------------- scratch (device globals; no allocation) ----------------
__device__ int   g_slot[MAXN];        // node -> compact slot (query index) or -1
__device__ float g_s[MAXQ * EMB];     // per-slot aggregated sum_e w_e * emb[src_e]
__device__ float g_c[MAXQ];           // per-slot sum_e w_e

// ---------------- kernels ----------------
// k0: init node->slot map only (0.4 MB)
__global__ void k_init_slot(int n_nodes) {
    int i = blockIdx.x * blockDim.x + threadIdx.x;
    if (i < n_nodes) g_slot[i] = -1;
}

// k1: mark queried nodes + zero accumulators (independent jobs, one launch)
__global__ void k_mark_zero(const int* __restrict__ query, int Q) {
    int i = blockIdx.x * blockDim.x + threadIdx.x;
    if (i < MAXQ * EMB / 4) ((float4*)g_s)[i] = make_float4(0.f, 0.f, 0.f, 0.f);
    if (i < MAXQ)           g_c[i] = 0.0f;
    if (i < Q)              atomicCAS(&g_slot[query[i]], -1, i);
}

__device__ __forceinline__ float4 scale4(float4 v, float w) {
    return make_float4(v.x * w, v.y * w, v.z * w, v.w * w);
}

// k2: fused filter + scatter.
// Each warp scans 32 consecutive edges (coalesced), ballots the hits
// (dst is a queried node, ~8.2%), then the full warp processes hits two at a
// time: gather emb[src] (2x LDG.128 per lane per edge, 4 in flight) and
// vector-RED into g_s[slot].
__global__ void __launch_bounds__(256) k_scatter_fused(
    const int* __restrict__ src, const int* __restrict__ dst,
    const float* __restrict__ ew, const float* __restrict__ emb, int E)
{
    int lane = threadIdx.x & 31;
    int gw   = (blockIdx.x * blockDim.x + threadIdx.x) >> 5;
    int nw   = (gridDim.x * blockDim.x) >> 5;

    for (int base = gw * 32; base < E; base += nw * 32) {
        int  e = base + lane;
        bool v = (e < E);
        int   d_n = v ? dst[e] : 0;
        int   s_n = v ? src[e] : 0;
        float w   = v ? ew[e]  : 0.f;
        int   sl  = v ? g_slot[d_n] : -1;
        unsigned mask = __ballot_sync(0xffffffffu, sl >= 0);

        while (mask) {
            int b0 = __ffs(mask) - 1; mask &= mask - 1;
            int b1 = -1;
            if (mask) { b1 = __ffs(mask) - 1; mask &= mask - 1; }
            int bb1 = (b1 < 0) ? b0 : b1;

            int   sn0 = __shfl_sync(0xffffffffu, s_n, b0);
            int   sl0 = __shfl_sync(0xffffffffu, sl,  b0);
            float w0  = __shfl_sync(0xffffffffu, w,   b0);
            int   sn1 = __shfl_sync(0xffffffffu, s_n, bb1);
            int   sl1 = __shfl_sync(0xffffffffu, sl,  bb1);
            float w1  = __shfl_sync(0xffffffffu, w,   bb1);

            const float4* r0 = (const float4*)(emb + (size_t)sn0 * EMB);
            const float4* r1 = (const float4*)(emb + (size_t)sn1 * EMB);
            float4 a0 = r0[lane], c0 = r0[lane + 32];
            float4 a1, c1;
            if (b1 >= 0) { a1 = r1[lane]; c1 = r1[lane + 32]; }

            float4* s0 = (float4*)(g_s + (size_t)sl0 * EMB);
            atomicAdd(&s0[lane],      scale4(a0, w0));
            atomicAdd(&s0[lane + 32], scale4(c0, w0));
            if (b1 >= 0) {
                float4* s1 = (float4*)(g_s + (size_t)sl1 * EMB);
                atomicAdd(&s1[lane],      scale4(a1, w1));
                atomicAdd(&s1[lane + 32], scale4(c1, w1));
            }
            if (lane == 0) {
                atomicAdd(&g_c[sl0], w0);
                if (b1 >= 0) atomicAdd(&g_c[sl1], w1);
            }
        }
    }
}

// ---------------- fused readout ----------------
// out[q] = Wr . relu(Ws@emb[node_q] + Wn@s[slot_q] + bs + c_q*bn) + br
// Register-tiled [64q x 512k] x [512k x 64o] GEMM, K in 2 chunks of 256.
#define QB   64                 // queries per block
#define KC   256                // k per chunk
#define WROW 68                 // padded row (floats), 16B aligned (68*4=272)
#define RD_SMEM ((KC * WROW * 2 + QB) * 4 + QB * 4 * 2)

__global__ void __launch_bounds__(256) k_readout(
    const float* __restrict__ emb, const float* __restrict__ Ws,
    const float* __restrict__ bs,  const float* __restrict__ Wn,
    const float* __restrict__ bn,  const float* __restrict__ Wr,
    const float* __restrict__ br,  const int* __restrict__ query,
    float* __restrict__ out, int Q)
{
    extern __shared__ float sm[];
    float* Wsm   = sm;                         // [KC][WROW]  (k-major, o contiguous)
    float* gsm   = sm + KC * WROW;             // [KC][WROW]  (k-major, q contiguous)
    float* csm   = gsm + KC * WROW;            // [QB]
    int*   nodes = (int*)(csm + QB);           // [QB]
    int*   slots = nodes + QB;                 // [QB]

    int tid   = threadIdx.x;
    int qbase = blockIdx.x * QB;

    if (tid < QB) {
        int q = qbase + tid;
        int node = (q < Q) ? query[q] : query[0];
        nodes[tid] = node;
        int sl = g_slot[node];
        slots[tid] = sl;
        csm[tid] = g_c[sl];
    }
    __syncthreads();

    int lane  = tid & 31;
    int w     = tid >> 5;
    int o_idx = lane & 15;          // thread outputs: o = 4*o_idx .. +3
    int q_idx = lane >> 4;          // 0/1
    int qw    = w * 8 + q_idx * 4;  // thread queries: qw .. qw+3 (block-local)

    float acc[4][4];                // [qi][oj]
#pragma unroll
    for (int a = 0; a < 4; ++a)
#pragma unroll
        for (int b = 0; b < 4; ++b) acc[a][b] = 0.f;

#pragma unroll
    for (int t = 0; t < 2; ++t) {
        // Stage weights transposed: Wsm[k][o] = W[o][k]
        const float* W = t ? Wn : Ws;
        for (int idx = tid; idx < HID * KC; idx += 256) {
            int k = idx & (KC - 1), o = idx >> 8;   // coalesced LDG
            Wsm[k * WROW + o] = W[o * EMB + k];
        }
        // Stage activations transposed: gsm[k][q] = row_q[k]
        for (int idx = tid; idx < QB * (KC / 4); idx += 256) {
            int q  = idx & (QB - 1);
            int kb = idx >> 6;
            const float* row = t ? (g_s + (size_t)slots[q] * EMB)
                                 : (emb + (size_t)nodes[q] * EMB);
            float4 v = ((const float4*)row)[kb];
            int k = kb * 4;
            gsm[(k + 0) * WROW + q] = v.x;
            gsm[(k + 1) * WROW + q] = v.y;
            gsm[(k + 2) * WROW + q] = v.z;
            gsm[(k + 3) * WROW + q] = v.w;
        }
        __syncthreads();

#pragma unroll 4
        for (int k = 0; k < KC; ++k) {
            float4 wv = *(const float4*)&Wsm[k * WROW + 4 * o_idx];
            float4 gv = *(const float4*)&gsm[k * WROW + qw];
            acc[0][0] += gv.x * wv.x; acc[0][1] += gv.x * wv.y;
            acc[0][2] += gv.x * wv.z; acc[0][3] += gv.x * wv.w;
            acc[1][0] += gv.y * wv.x; acc[1][1] += gv.y * wv.y;
            acc[1][2] += gv.y * wv.z; acc[1][3] += gv.y * wv.w;
            acc[2][0] += gv.z * wv.x; acc[2][1] += gv.z * wv.y;
            acc[2][2] += gv.z * wv.z; acc[2][3] += gv.z * wv.w;
            acc[3][0] += gv.w * wv.x; acc[3][1] += gv.w * wv.y;
            acc[3][2] += gv.w * wv.z; acc[3][3] += gv.w * wv.w;
        }
        __syncthreads();
    }

    // Epilogue: h = relu(acc + bs + c*bn); r_q = sum_o Wr[o]*h ; reduce over o lanes
    int o0 = 4 * o_idx;
    float4 bsv = *(const float4*)&bs[o0];
    float4 bnv = *(const float4*)&bn[o0];
    float4 wrv = *(const float4*)&Wr[o0];
    float  brv = br[0];
#pragma unroll
    for (int qi = 0; qi < 4; ++qi) {
        float cc = csm[qw + qi];
        float r = wrv.x * fmaxf(acc[qi][0] + bsv.x + cc * bnv.x, 0.f)
                + wrv.y * fmaxf(acc[qi][1] + bsv.y + cc * bnv.y, 0.f)
                + wrv.z * fmaxf(acc[qi][2] + bsv.z + cc * bnv.z, 0.f)
                + wrv.w * fmaxf(acc[qi][3] + bsv.w + cc * bnv.w, 0.f);
#pragma unroll
        for (int off = 8; off > 0; off >>= 1) r += __shfl_xor_sync(0xffffffffu, r, off);
        int q = qbase + qw + qi;
        if (o_idx == 0 && q < Q) out[q] = r + brv;
    }
}

// ---------------- launch ----------------
extern "C" void kernel_launch(void* const* d_in, const int* in_sizes, int n_in,
                              void* d_out, int out_size) {
    const float* emb = (const float*)d_in[0];
    const float* ew  = (const float*)d_in[1];
    const float* Ws  = (const float*)d_in[2];
    const float* bs  = (const float*)d_in[3];
    const float* Wn  = (const float*)d_in[4];
    const float* bn  = (const float*)d_in[5];
    const float* Wr  = (const float*)d_in[6];
    const float* br  = (const float*)d_in[7];
    const int*   src = (const int*)d_in[8];
    const int*   dst = (const int*)d_in[9];
    const int*   qry = (const int*)d_in[10];

    int N = in_sizes[0] / EMB;
    int E = in_sizes[8];
    int Q = in_sizes[10];

    cudaFuncSetAttribute(k_readout, cudaFuncAttributeMaxDynamicSharedMemorySize, RD_SMEM);

    k_init_slot    <<<(N + 255) / 256, 256>>>(N);
    k_mark_zero    <<<(MAXQ * EMB / 4 + 255) / 256, 256>>>(qry, Q);
    k_scatter_fused<<<1184, 256>>>(src, dst, ew, emb, E);
    k_readout      <<<(Q + QB - 1) / QB, 256, RD_SMEM>>>(emb, Ws, bs, Wn, bn, Wr, br, qry,
                                                         (float*)d_out, Q);
}

// round 4
// speedup vs baseline: 1.5563x; 1.0157x over previous
#include <cuda_runtime.h>

#define EMB 256
#define HID 64
#define MAXN 100000
#define MAXE 1200000
#define MAXQ 8192

// ---------------- scratch (device globals; no allocation) ----------------
__device__ int   g_slot[MAXN];        // node -> compact slot (query index) or -1
__device__ float g_s[MAXQ * EMB];     // per-slot aggregated sum_e w_e * emb[src_e]
__device__ float g_c[MAXQ];           // per-slot sum_e w_e

// ---------------- kernels ----------------
__global__ void k_init_slot(int n_nodes) {
    int i = blockIdx.x * blockDim.x + threadIdx.x;
    if (i < n_nodes) g_slot[i] = -1;
}

__global__ void k_mark_zero(const int* __restrict__ query, int Q) {
    int i = blockIdx.x * blockDim.x + threadIdx.x;
    if (i < MAXQ * EMB / 4) ((float4*)g_s)[i] = make_float4(0.f, 0.f, 0.f, 0.f);
    if (i < MAXQ)           g_c[i] = 0.0f;
    if (i < Q)              atomicCAS(&g_slot[query[i]], -1, i);
}

__device__ __forceinline__ float4 scale4(float4 v, float w) {
    return make_float4(v.x * w, v.y * w, v.z * w, v.w * w);
}

// Fused filter + scatter: warp scans 32 edges, ballots hits (~8.2%), processes
// hits two at a time with full-warp gathers and vector RED into g_s.
__global__ void __launch_bounds__(256) k_scatter_fused(
    const int* __restrict__ src, const int* __restrict__ dst,
    const float* __restrict__ ew, const float* __restrict__ emb, int E)
{
    int lane = threadIdx.x & 31;
    int gw   = (blockIdx.x * blockDim.x + threadIdx.x) >> 5;
    int nw   = (gridDim.x * blockDim.x) >> 5;

    for (int base = gw * 32; base < E; base += nw * 32) {
        int  e = base + lane;
        bool v = (e < E);
        int   d_n = v ? dst[e] : 0;
        int   s_n = v ? src[e] : 0;
        float w   = v ? ew[e]  : 0.f;
        int   sl  = v ? g_slot[d_n] : -1;
        unsigned mask = __ballot_sync(0xffffffffu, sl >= 0);

        while (mask) {
            int b0 = __ffs(mask) - 1; mask &= mask - 1;
            int b1 = -1;
            if (mask) { b1 = __ffs(mask) - 1; mask &= mask - 1; }
            int bb1 = (b1 < 0) ? b0 : b1;

            int   sn0 = __shfl_sync(0xffffffffu, s_n, b0);
            int   sl0 = __shfl_sync(0xffffffffu, sl,  b0);
            float w0  = __shfl_sync(0xffffffffu, w,   b0);
            int   sn1 = __shfl_sync(0xffffffffu, s_n, bb1);
            int   sl1 = __shfl_sync(0xffffffffu, sl,  bb1);
            float w1  = __shfl_sync(0xffffffffu, w,   bb1);

            const float4* r0 = (const float4*)(emb + (size_t)sn0 * EMB);
            const float4* r1 = (const float4*)(emb + (size_t)sn1 * EMB);
            float4 a0 = r0[lane], c0 = r0[lane + 32];
            float4 a1, c1;
            if (b1 >= 0) { a1 = r1[lane]; c1 = r1[lane + 32]; }

            float4* s0 = (float4*)(g_s + (size_t)sl0 * EMB);
            atomicAdd(&s0[lane],      scale4(a0, w0));
            atomicAdd(&s0[lane + 32], scale4(c0, w0));
            if (b1 >= 0) {
                float4* s1 = (float4*)(g_s + (size_t)sl1 * EMB);
                atomicAdd(&s1[lane],      scale4(a1, w1));
                atomicAdd(&s1[lane + 32], scale4(c1, w1));
            }
            if (lane == 0) {
                atomicAdd(&g_c[sl0], w0);
                if (b1 >= 0) atomicAdd(&g_c[sl1], w1);
            }
        }
    }
}

// ---------------- fused readout ----------------
// out[q] = Wr . relu(Ws@emb[node_q] + Wn@s[slot_q] + bs + c_q*bn) + br
// [64q x 512k] x [512k x 64o] register-tiled GEMM, 512 threads (16 warps),
// warp tile 4q x 64o, thread tile 2q x 4o. K in 2 chunks of 256.
#define QB   64
#define KC   256
#define WROW 68                 // padded row (floats), 272 B
#define RD_SMEM ((KC * WROW * 2 + QB) * 4 + QB * 4 * 2)

__global__ void __launch_bounds__(512) k_readout(
    const float* __restrict__ emb, const float* __restrict__ Ws,
    const float* __restrict__ bs,  const float* __restrict__ Wn,
    const float* __restrict__ bn,  const float* __restrict__ Wr,
    const float* __restrict__ br,  const int* __restrict__ query,
    float* __restrict__ out, int Q)
{
    extern __shared__ float sm[];
    float* Wsm   = sm;                         // [KC][WROW]  (k-major, o contiguous)
    float* gsm   = sm + KC * WROW;             // [KC][WROW]  (k-major, q contiguous)
    float* csm   = gsm + KC * WROW;            // [QB]
    int*   nodes = (int*)(csm + QB);           // [QB]
    int*   slots = nodes + QB;                 // [QB]

    int tid   = threadIdx.x;
    int qbase = blockIdx.x * QB;

    if (tid < QB) {
        int q = qbase + tid;
        int node = (q < Q) ? query[q] : query[0];
        nodes[tid] = node;
        int sl = g_slot[node];
        slots[tid] = sl;
        csm[tid] = g_c[sl];
    }
    __syncthreads();

    int lane  = tid & 31;
    int w     = tid >> 5;           // 0..15
    int o_idx = lane & 15;          // thread outputs: o = 4*o_idx .. +3
    int q_idx = lane >> 4;          // 0/1
    int qloc  = w * 4 + q_idx * 2;  // thread queries: qloc, qloc+1 (block-local)

    float acc[2][4];
#pragma unroll
    for (int a = 0; a < 2; ++a)
#pragma unroll
        for (int b = 0; b < 4; ++b) acc[a][b] = 0.f;

#pragma unroll
    for (int t = 0; t < 2; ++t) {
        // Stage weights transposed: Wsm[k][o] = W[o][k]
        const float* W = t ? Wn : Ws;
        for (int idx = tid; idx < HID * KC; idx += 512) {
            int k = idx & (KC - 1), o = idx >> 8;   // coalesced LDG
            Wsm[k * WROW + o] = W[o * EMB + k];
        }
        // Stage activations transposed: gsm[k][q] = row_q[k]
        for (int idx = tid; idx < QB * (KC / 4); idx += 512) {
            int q  = idx & (QB - 1);
            int kb = idx >> 6;
            const float* row = t ? (g_s + (size_t)slots[q] * EMB)
                                 : (emb + (size_t)nodes[q] * EMB);
            float4 v = ((const float4*)row)[kb];
            int k = kb * 4;
            gsm[(k + 0) * WROW + q] = v.x;
            gsm[(k + 1) * WROW + q] = v.y;
            gsm[(k + 2) * WROW + q] = v.z;
            gsm[(k + 3) * WROW + q] = v.w;
        }
        __syncthreads();

        const float* wp = Wsm + 4 * o_idx;
        const float* gp = gsm + qloc;
#pragma unroll 8
        for (int k = 0; k < KC; ++k) {
            float4 wv = *(const float4*)(wp + k * WROW);
            float2 gv = *(const float2*)(gp + k * WROW);
            acc[0][0] += gv.x * wv.x; acc[0][1] += gv.x * wv.y;
            acc[0][2] += gv.x * wv.z; acc[0][3] += gv.x * wv.w;
            acc[1][0] += gv.y * wv.x; acc[1][1] += gv.y * wv.y;
            acc[1][2] += gv.y * wv.z; acc[1][3] += gv.y * wv.w;
        }
        __syncthreads();
    }

    // Epilogue: h = relu(acc + bs + c*bn); r_q = sum_o Wr[o]*h; reduce over o lanes
    int o0 = 4 * o_idx;
    float4 bsv = *(const float4*)&bs[o0];
    float4 bnv = *(const float4*)&bn[o0];
    float4 wrv = *(const float4*)&Wr[o0];
    float  brv = br[0];
#pragma unroll
    for (int qi = 0; qi < 2; ++qi) {
        float cc = csm[qloc + qi];
        float r = wrv.x * fmaxf(acc[qi][0] + bsv.x + cc * bnv.x, 0.f)
                + wrv.y * fmaxf(acc[qi][1] + bsv.y + cc * bnv.y, 0.f)
                + wrv.z * fmaxf(acc[qi][2] + bsv.z + cc * bnv.z, 0.f)
                + wrv.w * fmaxf(acc[qi][3] + bsv.w + cc * bnv.w, 0.f);
#pragma unroll
        for (int off = 8; off > 0; off >>= 1) r += __shfl_xor_sync(0xffffffffu, r, off);
        int q = qbase + qloc + qi;
        if (o_idx == 0 && q < Q) out[q] = r + brv;
    }
}

// ---------------- launch ----------------
extern "C" void kernel_launch(void* const* d_in, const int* in_sizes, int n_in,
                              void* d_out, int out_size) {
    const float* emb = (const float*)d_in[0];
    const float* ew  = (const float*)d_in[1];
    const float* Ws  = (const float*)d_in[2];
    const float* bs  = (const float*)d_in[3];
    const float* Wn  = (const float*)d_in[4];
    const float* bn  = (const float*)d_in[5];
    const float* Wr  = (const float*)d_in[6];
    const float* br  = (const float*)d_in[7];
    const int*   src = (const int*)d_in[8];
    const int*   dst = (const int*)d_in[9];
    const int*   qry = (const int*)d_in[10];

    int N = in_sizes[0] / EMB;
    int E = in_sizes[8];
    int Q = in_sizes[10];

    cudaFuncSetAttribute(k_readout, cudaFuncAttributeMaxDynamicSharedMemorySize, RD_SMEM);

    k_init_slot    <<<(N + 255) / 256, 256>>>(N);
    k_mark_zero    <<<(MAXQ * EMB / 4 + 255) / 256, 256>>>(qry, Q);
    k_scatter_fused<<<1184, 256>>>(src, dst, ew, emb, E);
    k_readout      <<<(Q + QB - 1) / QB, 512, RD_SMEM>>>(emb, Ws, bs, Wn, bn, Wr, br, qry,
                                                         (float*)d_out, Q);
}

// round 5
// speedup vs baseline: 1.7943x; 1.1530x over previous
#include <cuda_runtime.h>
#include <cstdint>

#define EMB 256
#define HID 64
#define MAXN 100000
#define MAXQ 8192

// ---------------- scratch (device globals; no allocation) ----------------
__device__ int   g_slot[MAXN];        // node -> compact slot (query index) or -1
__device__ float g_s[MAXQ * EMB];     // per-slot aggregated sum_e w_e * emb[src_e]
__device__ float g_c[MAXQ];           // per-slot sum_e w_e

// ---------------- kernels ----------------
__global__ void k_init_slot(int n_nodes) {
    int i = blockIdx.x * blockDim.x + threadIdx.x;
    if (i < n_nodes) g_slot[i] = -1;
}

__global__ void k_mark_zero(const int* __restrict__ query, int Q) {
    int i = blockIdx.x * blockDim.x + threadIdx.x;
    if (i < MAXQ * EMB / 4) ((float4*)g_s)[i] = make_float4(0.f, 0.f, 0.f, 0.f);
    if (i < MAXQ)           g_c[i] = 0.0f;
    if (i < Q)              atomicCAS(&g_slot[query[i]], -1, i);
}

__device__ __forceinline__ float4 scale4(float4 v, float w) {
    return make_float4(v.x * w, v.y * w, v.z * w, v.w * w);
}

// Fused filter + scatter: warp scans 32 edges, ballots hits (~8.2%), processes
// hits two at a time with full-warp gathers and vector RED into g_s.
__global__ void __launch_bounds__(256) k_scatter_fused(
    const int* __restrict__ src, const int* __restrict__ dst,
    const float* __restrict__ ew, const float* __restrict__ emb, int E)
{
    int lane = threadIdx.x & 31;
    int gw   = (blockIdx.x * blockDim.x + threadIdx.x) >> 5;
    int nw   = (gridDim.x * blockDim.x) >> 5;

    for (int base = gw * 32; base < E; base += nw * 32) {
        int  e = base + lane;
        bool v = (e < E);
        int   d_n = v ? dst[e] : 0;
        int   s_n = v ? src[e] : 0;
        float w   = v ? ew[e]  : 0.f;
        int   sl  = v ? g_slot[d_n] : -1;
        unsigned mask = __ballot_sync(0xffffffffu, sl >= 0);

        while (mask) {
            int b0 = __ffs(mask) - 1; mask &= mask - 1;
            int b1 = -1;
            if (mask) { b1 = __ffs(mask) - 1; mask &= mask - 1; }
            int bb1 = (b1 < 0) ? b0 : b1;

            int   sn0 = __shfl_sync(0xffffffffu, s_n, b0);
            int   sl0 = __shfl_sync(0xffffffffu, sl,  b0);
            float w0  = __shfl_sync(0xffffffffu, w,   b0);
            int   sn1 = __shfl_sync(0xffffffffu, s_n, bb1);
            int   sl1 = __shfl_sync(0xffffffffu, sl,  bb1);
            float w1  = __shfl_sync(0xffffffffu, w,   bb1);

            const float4* r0 = (const float4*)(emb + (size_t)sn0 * EMB);
            const float4* r1 = (const float4*)(emb + (size_t)sn1 * EMB);
            float4 a0 = r0[lane], c0 = r0[lane + 32];
            float4 a1, c1;
            if (b1 >= 0) { a1 = r1[lane]; c1 = r1[lane + 32]; }

            float4* s0 = (float4*)(g_s + (size_t)sl0 * EMB);
            atomicAdd(&s0[lane],      scale4(a0, w0));
            atomicAdd(&s0[lane + 32], scale4(c0, w0));
            if (b1 >= 0) {
                float4* s1 = (float4*)(g_s + (size_t)sl1 * EMB);
                atomicAdd(&s1[lane],      scale4(a1, w1));
                atomicAdd(&s1[lane + 32], scale4(c1, w1));
            }
            if (lane == 0) {
                atomicAdd(&g_c[sl0], w0);
                if (b1 >= 0) atomicAdd(&g_c[sl1], w1);
            }
        }
    }
}

// ---------------- fused readout ----------------
// out[q] = Wr . relu(Ws@emb[node_q] + Wn@s[slot_q] + bs + c_q*bn) + br
// 512 threads, split-K: warps 0-7 compute Ws@emb (k 0..255), warps 8-15
// compute Wn@s (k 0..255); partials combined via smem. Thread tile 4q x 4o
// computed as 8x fma.rn.f32x2 (FFMA2, 2x fp32 pipe rate vs 3-reg FFMA).
#define QB   64
#define KSUB 128
#define WROW 68                     // padded row (floats); 272 B = 17*16
#define W0F  0
#define W1F  (KSUB * WROW)
#define G0F  (2 * KSUB * WROW)
#define G1F  (3 * KSUB * WROW)
#define AUXF (4 * KSUB * WROW)
#define RD_SMEM ((AUXF + QB) * 4 + QB * 8)

__global__ void __launch_bounds__(512) k_readout(
    const float* __restrict__ emb, const float* __restrict__ Ws,
    const float* __restrict__ bs,  const float* __restrict__ Wn,
    const float* __restrict__ bn,  const float* __restrict__ Wr,
    const float* __restrict__ br,  const int* __restrict__ query,
    float* __restrict__ out, int Q)
{
    extern __shared__ float sm[];
    float* csm   = sm + AUXF;
    int*   nodes = (int*)(csm + QB);
    int*   slots = nodes + QB;

    int tid   = threadIdx.x;
    int qbase = blockIdx.x * QB;

    if (tid < QB) {
        int q = qbase + tid;
        int node = (q < Q) ? query[q] : query[0];
        nodes[tid] = node;
        slots[tid] = g_slot[node];
        csm[tid]   = g_c[g_slot[node]];
    }
    __syncthreads();

    int lane  = tid & 31;
    int w     = tid >> 5;
    int h     = w >> 3;             // 0: self (Ws,emb)   1: neigh (Wn,g_s)
    int wl    = w & 7;
    int o_idx = lane & 15;          // o = 4*o_idx .. +3
    int q_idx = lane >> 4;
    int qloc  = wl * 8 + q_idx * 4; // q = qloc .. qloc+3 (block-local)

    uint32_t smem_u32;
    asm("{ .reg .u64 t; cvta.to.shared.u64 t, %1; cvt.u32.u64 %0, t; }"
        : "=r"(smem_u32) : "l"(sm));

    unsigned long long a00 = 0, a01 = 0, a10 = 0, a11 = 0;
    unsigned long long a20 = 0, a21 = 0, a30 = 0, a31 = 0;

    int woff = h ? W1F : W0F;
    int goff = h ? G1F : G0F;

#define FMA2(ACC, WV, GV) \
    asm("fma.rn.f32x2 %0, %1, %2, %0;" : "+l"(ACC) : "l"(WV), "l"(GV))

#define KSTEP(IMM, FOFF) { \
    unsigned long long wv0, wv1; \
    asm volatile("ld.shared.v2.b64 {%0, %1}, [%2+" IMM "];" \
                 : "=l"(wv0), "=l"(wv1) : "r"(wb)); \
    float4 gv = *(const float4*)(gp + (FOFF)); \
    uint32_t ux = __float_as_uint(gv.x), uy = __float_as_uint(gv.y); \
    uint32_t uz = __float_as_uint(gv.z), uw = __float_as_uint(gv.w); \
    unsigned long long g0, g1, g2, g3; \
    asm("mov.b64 %0, {%1, %1};" : "=l"(g0) : "r"(ux)); \
    asm("mov.b64 %0, {%1, %1};" : "=l"(g1) : "r"(uy)); \
    asm("mov.b64 %0, {%1, %1};" : "=l"(g2) : "r"(uz)); \
    asm("mov.b64 %0, {%1, %1};" : "=l"(g3) : "r"(uw)); \
    FMA2(a00, wv0, g0); FMA2(a01, wv1, g0); \
    FMA2(a10, wv0, g1); FMA2(a11, wv1, g1); \
    FMA2(a20, wv0, g2); FMA2(a21, wv1, g2); \
    FMA2(a30, wv0, g3); FMA2(a31, wv1, g3); }

    for (int sc = 0; sc < 2; ++sc) {
        int k0 = sc * KSUB;
        // Stage weights transposed, lanes across o (conflict-free STS):
        // buf[k][o] = W[o][k0+k]
        for (int idx = tid; idx < 4096; idx += 512) {
            int o  = idx & 63;
            int kb = (idx >> 6) & 31;
            int hb = idx >> 11;
            const float* W = hb ? Wn : Ws;
            float4 v = *(const float4*)&W[o * EMB + k0 + 4 * kb];
            float* buf = sm + (hb ? W1F : W0F) + (4 * kb) * WROW + o;
            buf[0] = v.x; buf[WROW] = v.y; buf[2 * WROW] = v.z; buf[3 * WROW] = v.w;
        }
        // Stage activations transposed, lanes across q (conflict-free STS):
        // buf[k][q] = row_q[k0+k]
        for (int idx = tid; idx < 4096; idx += 512) {
            int q  = idx & 63;
            int kb = (idx >> 6) & 31;
            int hb = idx >> 11;
            const float* row = hb ? (g_s + (size_t)slots[q] * EMB)
                                  : (emb + (size_t)nodes[q] * EMB);
            float4 v = ((const float4*)row)[(k0 >> 2) + kb];
            float* buf = sm + (hb ? G1F : G0F) + (4 * kb) * WROW + q;
            buf[0] = v.x; buf[WROW] = v.y; buf[2 * WROW] = v.z; buf[3 * WROW] = v.w;
        }
        __syncthreads();

        uint32_t wb = smem_u32 + (uint32_t)(woff + 4 * o_idx) * 4u;
        const float* gp = sm + goff + qloc;
#pragma unroll 1
        for (int k4 = 0; k4 < KSUB / 4; ++k4) {
            KSTEP("0",   0)
            KSTEP("272", WROW)
            KSTEP("544", 2 * WROW)
            KSTEP("816", 3 * WROW)
            wb += 1088;
            gp += 4 * WROW;
        }
        __syncthreads();
    }

    // Combine halves through smem (reuse G0 region), then epilogue on half 0.
    float* accsm = sm + G0F;
    if (h == 1) {
        float4 v;
        v.x = __uint_as_float((uint32_t)a00); v.y = __uint_as_float((uint32_t)(a00 >> 32));
        v.z = __uint_as_float((uint32_t)a01); v.w = __uint_as_float((uint32_t)(a01 >> 32));
        *(float4*)&accsm[(qloc + 0) * WROW + 4 * o_idx] = v;
        v.x = __uint_as_float((uint32_t)a10); v.y = __uint_as_float((uint32_t)(a10 >> 32));
        v.z = __uint_as_float((uint32_t)a11); v.w = __uint_as_float((uint32_t)(a11 >> 32));
        *(float4*)&accsm[(qloc + 1) * WROW + 4 * o_idx] = v;
        v.x = __uint_as_float((uint32_t)a20); v.y = __uint_as_float((uint32_t)(a20 >> 32));
        v.z = __uint_as_float((uint32_t)a21); v.w = __uint_as_float((uint32_t)(a21 >> 32));
        *(float4*)&accsm[(qloc + 2) * WROW + 4 * o_idx] = v;
        v.x = __uint_as_float((uint32_t)a30); v.y = __uint_as_float((uint32_t)(a30 >> 32));
        v.z = __uint_as_float((uint32_t)a31); v.w = __uint_as_float((uint32_t)(a31 >> 32));
        *(float4*)&accsm[(qloc + 3) * WROW + 4 * o_idx] = v;
    }
    __syncthreads();

    if (h == 0) {
        int o0 = 4 * o_idx;
        float4 bsv = *(const float4*)&bs[o0];
        float4 bnv = *(const float4*)&bn[o0];
        float4 wrv = *(const float4*)&Wr[o0];
        float  brv = br[0];
        unsigned long long pa0[4] = {a00, a10, a20, a30};
        unsigned long long pa1[4] = {a01, a11, a21, a31};
#pragma unroll
        for (int qi = 0; qi < 4; ++qi) {
            float4 p = *(const float4*)&accsm[(qloc + qi) * WROW + o0];
            float x0 = __uint_as_float((uint32_t)pa0[qi])         + p.x;
            float x1 = __uint_as_float((uint32_t)(pa0[qi] >> 32)) + p.y;
            float x2 = __uint_as_float((uint32_t)pa1[qi])         + p.z;
            float x3 = __uint_as_float((uint32_t)(pa1[qi] >> 32)) + p.w;
            float cc = csm[qloc + qi];
            float r = wrv.x * fmaxf(x0 + bsv.x + cc * bnv.x, 0.f)
                    + wrv.y * fmaxf(x1 + bsv.y + cc * bnv.y, 0.f)
                    + wrv.z * fmaxf(x2 + bsv.z + cc * bnv.z, 0.f)
                    + wrv.w * fmaxf(x3 + bsv.w + cc * bnv.w, 0.f);
#pragma unroll
            for (int off = 8; off > 0; off >>= 1)
                r += __shfl_xor_sync(0xffffffffu, r, off);
            int q = qbase + qloc + qi;
            if (o_idx == 0 && q < Q) out[q] = r + brv;
        }
    }
}

// ---------------- launch ----------------
extern "C" void kernel_launch(void* const* d_in, const int* in_sizes, int n_in,
                              void* d_out, int out_size) {
    const float* emb = (const float*)d_in[0];
    const float* ew  = (const float*)d_in[1];
    const float* Ws  = (const float*)d_in[2];
    const float* bs  = (const float*)d_in[3];
    const float* Wn  = (const float*)d_in[4];
    const float* bn  = (const float*)d_in[5];
    const float* Wr  = (const float*)d_in[6];
    const float* br  = (const float*)d_in[7];
    const int*   src = (const int*)d_in[8];
    const int*   dst = (const int*)d_in[9];
    const int*   qry = (const int*)d_in[10];

    int N = in_sizes[0] / EMB;
    int E = in_sizes[8];
    int Q = in_sizes[10];

    cudaFuncSetAttribute(k_readout, cudaFuncAttributeMaxDynamicSharedMemorySize, RD_SMEM);

    k_init_slot    <<<(N + 255) / 256, 256>>>(N);
    k_mark_zero    <<<(MAXQ * EMB / 4 + 255) / 256, 256>>>(qry, Q);
    k_scatter_fused<<<1184, 256>>>(src, dst, ew, emb, E);
    k_readout      <<<(Q + QB - 1) / QB, 512, RD_SMEM>>>(emb, Ws, bs, Wn, bn, Wr, br, qry,
                                                         (float*)d_out, Q);
}